// round 13
// baseline (speedup 1.0000x reference)
#include <cuda_runtime.h>
#include <math.h>
#include <stdint.h>

#define BB 64
#define SS 1024
#define EE 128
#define PC 640              // gK(128) gV(128) logitK(128) P1(128) P2(128)
#define INV_SQRT_E  0.08838834764831845f
#define FULLM 0xffffffffu

extern "C" __device__ float __nv_expf(float);
extern "C" __device__ float __nv_logf(float);

// XLA f32 tanh (frozen numerics — do not touch)
__device__ __forceinline__ float xla_tanh(float x) {
    float xc = fminf(fmaxf(x, -7.99881172180175781f), 7.99881172180175781f);
    float x2 = __fmul_rn(xc, xc);
    float p = __fadd_rn(__fmul_rn(x2, -2.76076847742355e-16f), 2.00018790482477e-13f);
    p = __fadd_rn(__fmul_rn(x2, p), -8.60467152213735e-11f);
    p = __fadd_rn(__fmul_rn(x2, p), 5.12229709037114e-08f);
    p = __fadd_rn(__fmul_rn(x2, p), 1.48572235717979e-05f);
    p = __fadd_rn(__fmul_rn(x2, p), 6.37261928875436e-04f);
    p = __fadd_rn(__fmul_rn(x2, p), 4.89352455891786e-03f);
    p = __fmul_rn(xc, p);
    float q = __fadd_rn(__fmul_rn(x2, 1.19825839466702e-06f), 1.18534705686654e-04f);
    q = __fadd_rn(__fmul_rn(x2, q), 2.26843463243900e-03f);
    q = __fadd_rn(__fmul_rn(x2, q), 4.89352518554385e-03f);
    float r = __fdiv_rn(p, q);
    return (fabsf(x) < 0.0004f) ? x : r;
}

__device__ __forceinline__ float fmax4(float4 v) {
    return fmaxf(fmaxf(v.x, v.y), fmaxf(v.z, v.w));
}

// ---- cluster / DSMEM helpers ----
__device__ __forceinline__ uint32_t cluster_rank() {
    uint32_t r; asm("mov.u32 %0, %%cluster_ctarank;" : "=r"(r)); return r;
}
__device__ __forceinline__ uint32_t smem_u32(const void* p) {
    return (uint32_t)__cvta_generic_to_shared(p);
}
__device__ __forceinline__ uint32_t mapa_sh(uint32_t a, uint32_t rk) {
    uint32_t r; asm("mapa.shared::cluster.u32 %0, %1, %2;" : "=r"(r) : "r"(a), "r"(rk));
    return r;
}
__device__ __forceinline__ void stc_f32(uint32_t a, float v) {
    asm volatile("st.shared::cluster.f32 [%0], %1;" :: "r"(a), "f"(v));
}
__device__ __forceinline__ void stc_v4(uint32_t a, float4 v) {
    asm volatile("st.shared::cluster.v4.f32 [%0], {%1,%2,%3,%4};"
                 :: "r"(a), "f"(v.x), "f"(v.y), "f"(v.z), "f"(v.w));
}
#define CLUSTER_SYNC() do { \
    asm volatile("barrier.cluster.arrive.aligned;" ::: "memory"); \
    asm volatile("barrier.cluster.wait.aligned;" ::: "memory"); } while (0)

__device__ float g_Wall[128 * PC];
__device__ float g_proj[(size_t)BB * SS * PC];   // 168 MB

// ============================================================================
__global__ void prep_kernel(const float* __restrict__ W_node,
                            const float* __restrict__ W_upd) {
    int tid = blockIdx.x * blockDim.x + threadIdx.x;
    int stride = blockDim.x * gridDim.x;
    for (int idx = tid; idx < 128 * 384; idx += stride) {
        int k = idx / 384, c = idx % 384;
        g_Wall[k * PC + c] = W_node[k * 384 + c];
    }
    for (int idx = tid; idx < 256 * 128; idx += stride) {
        int k2 = idx >> 7, j = idx & 127;
        float v = W_upd[idx];
        if (k2 < 128) g_Wall[k2 * PC + 384 + j] = v;
        else          g_Wall[(k2 - 128) * PC + 512 + j] = v;
    }
}

// ============================================================================
__global__ __launch_bounds__(256) void gemm_kernel(const float* __restrict__ A) {
    extern __shared__ float sh[];
    float* As = sh;              // [128][65]
    float* Bs = sh + 128 * 65;   // [128][128]
    int row0 = blockIdx.x * 64, col0 = blockIdx.y * 128, tid = threadIdx.x;

    for (int idx = tid; idx < 64 * 128; idx += 256) {
        int r = idx >> 7, k = idx & 127;
        As[k * 65 + r] = A[(size_t)(row0 + r) * 128 + k];
    }
    for (int idx = tid; idx < 128 * 128; idx += 256) {
        int k = idx >> 7, c = idx & 127;
        Bs[k * 128 + c] = g_Wall[k * PC + col0 + c];
    }
    __syncthreads();

    int tx = tid & 15, ty = tid >> 4;
    int r0 = ty * 4, c0 = tx * 8;
    float acc[4][8];
#pragma unroll
    for (int i = 0; i < 4; i++)
#pragma unroll
        for (int j = 0; j < 8; j++) acc[i][j] = 0.f;
#pragma unroll 8
    for (int k = 0; k < 128; k++) {
        float a0 = As[k*65+r0], a1 = As[k*65+r0+1], a2 = As[k*65+r0+2], a3 = As[k*65+r0+3];
        float4 b0 = *(float4*)&Bs[k*128+c0];
        float4 b1 = *(float4*)&Bs[k*128+c0+4];
        float bb[8] = {b0.x,b0.y,b0.z,b0.w,b1.x,b1.y,b1.z,b1.w};
#pragma unroll
        for (int j = 0; j < 8; j++) {
            acc[0][j] += a0*bb[j]; acc[1][j] += a1*bb[j];
            acc[2][j] += a2*bb[j]; acc[3][j] += a3*bb[j];
        }
    }
#pragma unroll
    for (int i = 0; i < 4; i++) {
        size_t o = (size_t)(row0+r0+i)*PC + col0 + c0;
        *(float4*)&g_proj[o]   = make_float4(acc[i][0],acc[i][1],acc[i][2],acc[i][3]);
        *(float4*)&g_proj[o+4] = make_float4(acc[i][4],acc[i][5],acc[i][6],acc[i][7]);
    }
}

// ============================================================================
// Decode: cluster of 2 CTAs per batch. CTA rank r owns logical warps
// r*16+0..15 (cities r*512..r*512+511). Streaming phases run on 16 warps
// with dual (local + DSMEM) stores; dense phases duplicated on both CTAs.
// All value-producing arithmetic orders identical to R12.
// ============================================================================
struct DS {
    float wout[128 * 128];
    float compat[8 * 1032];
    float part[32 * 128];
    float logits[1024];
    float q[128], hhat[128], phq[128], heads[128], glim[128];
    float redv8[8 * 32];  // [head][logical warp]
    float redv[32];       // per-logical-warp logit maxes
    float redv2[32];      // P3 warp exp sums | P8 pair-tree partials
    float redv3[32];      // P9 per-warp argmax value
    int   redi[32];       // P9 per-warp argmax index
};

__global__ __launch_bounds__(1024, 1) __cluster_dims__(2, 1, 1)
void decode_kernel(
    const float* __restrict__ enc,
    const float* __restrict__ W_ctx,
    const float* __restrict__ W_upd,
    const float* __restrict__ W_out,
    const float* __restrict__ W_ph,
    float* __restrict__ out)
{
    extern __shared__ char smem_raw[];
    DS& sm = *reinterpret_cast<DS*>(smem_raw);

    const int b = blockIdx.x >> 1, tid = threadIdx.x;
    const int lane = tid & 31, warp = tid >> 5;
    const uint32_t rank = cluster_rank();
    const float NEGINF = -INFINITY;

    // DSMEM peer delta (shared window is linear per rank)
    const uint32_t smbase = smem_u32(&sm);
    const int32_t pd = (int32_t)(mapa_sh(smbase, rank ^ 1) - smbase);

    const float* __restrict__ projb = g_proj + (size_t)b * SS * PC;
    const float* __restrict__ encb  = enc + (size_t)b * SS * EE;

    // ---- init (duplicated on both CTAs; numerics identical to R12) ----
    for (int idx = tid; idx < 128 * 128; idx += 1024)
        sm.wout[idx] = W_out[idx];
    {
        int e = tid & 127, g = tid >> 7;
        float acc = 0.f;
        for (int i = 0; i < 128; i++)
            acc += encb[(size_t)(g * 128 + i) * EE + e];
        sm.part[g * 128 + e] = acc;
    }
    __syncthreads();
    if (tid < 128) {
        float m = 0.f;
#pragma unroll
        for (int g = 0; g < 8; g++) m += sm.part[g * 128 + tid];
        sm.q[tid] = m * (1.0f / 1024.0f);
    }
    __syncthreads();
    if (tid < 128) {
        float h = 0.f;
#pragma unroll 8
        for (int k = 0; k < 128; k++) h += sm.q[k] * W_ctx[k * 128 + tid];
        sm.hhat[tid] = h;
    } else if (tid < 256) {
        int e = tid - 128;
        float p = 0.f;
#pragma unroll 8
        for (int k = 0; k < 256; k++) p += W_ph[k] * W_upd[k * 128 + e];
        sm.phq[e] = p;
    }
    __syncthreads();
    if (tid < 128) sm.q[tid] = sm.hhat[tid] + sm.phq[tid];
    __syncthreads();

    const int lw = (int)rank * 16 + warp;    // logical warp (valid for warp<16)
    unsigned wm = 0u;                        // mask bits for logical warp lw
    int first_r = 0;
    float pf_r = 0.f;
    double logp_sum = 0.0;

    for (int t = 0; t < SS; t++) {
        // ---- P1 (warps 0-15): compat own half + per-head max; dual-store ----
        if (warp < 16) {
            float4 qv = *(float4*)&sm.q[lane * 4];
            int h = lane >> 2;
            float mx = NEGINF;
#pragma unroll 8
            for (int i = 0; i < 32; i++) {
                int s = lw * 32 + i;
                float4 g = *(const float4*)(projb + (size_t)s * PC + lane * 4);
                float v = g.x*qv.x + g.y*qv.y + g.z*qv.z + g.w*qv.w;
                v += __shfl_xor_sync(FULLM, v, 1);
                v += __shfl_xor_sync(FULLM, v, 2);
                float cv = ((wm >> i) & 1u) ? NEGINF : v * 0.25f;
                mx = fmaxf(mx, cv);
                if ((lane & 3) == 0) {
                    sm.compat[h * 1032 + s] = cv;
                    stc_f32(smbase + (uint32_t)((char*)&sm.compat[h*1032+s] - (char*)&sm) + pd, cv);
                }
            }
            if ((lane & 3) == 0) {
                sm.redv8[h * 32 + lw] = mx;
                stc_f32(smbase + (uint32_t)((char*)&sm.redv8[h*32+lw] - (char*)&sm) + pd, mx);
            }
        }
        CLUSTER_SYNC();

        // ---- P3 (duplicated): hm order-free fmax + frozen exp chain + warp sum ----
        {
            int gh = tid >> 7, j = tid & 127;
            const float4* r8 = (const float4*)&sm.redv8[gh * 32];
            float hm = fmaxf(fmaxf(fmax4(r8[0]), fmax4(r8[1])),
                             fmaxf(fmax4(r8[2]), fmax4(r8[3])));
            hm = fmaxf(hm, fmaxf(fmaxf(fmax4(r8[4]), fmax4(r8[5])),
                                 fmaxf(fmax4(r8[6]), fmax4(r8[7]))));
            float se = 0.f;
#pragma unroll
            for (int ii = 0; ii < 8; ii++) {
                int idx = gh * 1032 + j + ii * 128;
                float ev = __nv_expf(sm.compat[idx] - hm);
                sm.compat[idx] = ev;
                se += ev;                         // frozen serial chain
            }
#pragma unroll
            for (int off = 16; off; off >>= 1)
                se += __shfl_xor_sync(FULLM, se, off);
            if (lane == 0) sm.redv2[warp] = se;
        }
        __syncthreads();

        // ---- P4 (warps 0-15): invs replay + heads partials; dual-store ----
        if (warp < 16) {
            int h = lane >> 2;
            float s4 = sm.redv2[h*4] + sm.redv2[h*4+1] + sm.redv2[h*4+2] + sm.redv2[h*4+3];
            float invs = 1.0f / s4;
            float4 acc = make_float4(0.f, 0.f, 0.f, 0.f);
#pragma unroll
            for (int i4 = 0; i4 < 8; i4++) {
                float4 c4 = *(const float4*)&sm.compat[h * 1032 + lw * 32 + i4 * 4];
                float av[4] = {c4.x, c4.y, c4.z, c4.w};
#pragma unroll
                for (int k = 0; k < 4; k++) {
                    int s = lw * 32 + i4 * 4 + k;
                    float a = av[k] * invs;       // masked: +0 (identity add)
                    float4 g = *(const float4*)(projb + (size_t)s * PC + 128 + lane * 4);
                    acc.x += a*g.x; acc.y += a*g.y; acc.z += a*g.z; acc.w += a*g.w;
                }
            }
            ((float4*)&sm.part[lw * 128])[lane] = acc;
            stc_v4(smbase + (uint32_t)((char*)&sm.part[lw*128 + lane*4] - (char*)&sm) + pd, acc);
        }
        CLUSTER_SYNC();

        // ---- P5 (duplicated): heads reduce (frozen 2-stage order) ----
        if (tid < 128) {
            float hsum = 0.f;
#pragma unroll
            for (int g = 0; g < 8; g++) {
                float pg = sm.part[(g*4+0)*128+tid] + sm.part[(g*4+1)*128+tid]
                         + sm.part[(g*4+2)*128+tid] + sm.part[(g*4+3)*128+tid];
                hsum += pg;
            }
            sm.heads[tid] = hsum;
        }
        __syncthreads();

        // ---- P6 (duplicated): glimpse (frozen chain) ----
        if (tid < 128) {
            float gl = 0.f;
#pragma unroll 8
            for (int f = 0; f < 128; f++) gl += sm.heads[f] * sm.wout[f*128+tid];
            sm.glim[tid] = gl;
        }
        __syncthreads();

        // ---- P7 (warps 0-15): 3-shfl butterfly dots + parallel tanh; dual-store ----
        if (warp < 16) {
            int g = lane >> 3, j = lane & 7;
            float4 h0 = *(float4*)&sm.glim[(j     ) * 4];
            float4 h1 = *(float4*)&sm.glim[(j +  8) * 4];
            float4 h2 = *(float4*)&sm.glim[(j + 16) * 4];
            float4 h3 = *(float4*)&sm.glim[(j + 24) * 4];
#pragma unroll
            for (int m = 0; m < 8; m++) {
                int s = lw * 32 + m * 4 + g;
                const float* row = projb + (size_t)s * PC + 256;
                float4 gA = *(const float4*)(row + (j     ) * 4);
                float4 gB = *(const float4*)(row + (j +  8) * 4);
                float4 gC = *(const float4*)(row + (j + 16) * 4);
                float4 gD = *(const float4*)(row + (j + 24) * 4);
                float dA = gA.x*h0.x + gA.y*h0.y + gA.z*h0.z + gA.w*h0.w;
                float dB = gB.x*h1.x + gB.y*h1.y + gB.z*h1.z + gB.w*h1.w;
                float dC = gC.x*h2.x + gC.y*h2.y + gC.z*h2.z + gC.w*h2.w;
                float dD = gD.x*h3.x + gD.y*h3.y + gD.z*h3.z + gD.w*h3.w;
                float t16a = dA + dC;
                float t16b = dB + dD;
                float v = t16a + t16b;
                v += __shfl_xor_sync(FULLM, v, 4);
                v += __shfl_xor_sync(FULLM, v, 2);
                v += __shfl_xor_sync(FULLM, v, 1);
                if (j == 0) sm.logits[s] = v;     // raw dot staged (local)
            }
            __syncwarp();
            {
                int s = lw * 32 + lane;
                float raw = sm.logits[s];
                float lv = ((wm >> lane) & 1u) ? NEGINF
                         : __fmul_rn(10.0f, xla_tanh(__fmul_rn(raw, INV_SQRT_E)));
                sm.logits[s] = lv;
                stc_f32(smbase + (uint32_t)((char*)&sm.logits[s] - (char*)&sm) + pd, lv);
                float v = lv;
#pragma unroll
                for (int off = 16; off; off >>= 1)
                    v = fmaxf(v, __shfl_xor_sync(FULLM, v, off));
                if (lane == 0) {
                    sm.redv[lw] = v;
                    stc_f32(smbase + (uint32_t)((char*)&sm.redv[lw] - (char*)&sm) + pd, v);
                }
            }
        }
        CLUSTER_SYNC();

        // ---- P8 (duplicated): m order-free fmax; frozen pair-exp tree ----
        float m_r;
        {
            const float4* rv = (const float4*)&sm.redv[0];
            m_r = fmaxf(fmaxf(fmax4(rv[0]), fmax4(rv[1])),
                        fmaxf(fmax4(rv[2]), fmax4(rv[3])));
            m_r = fmaxf(m_r, fmaxf(fmaxf(fmax4(rv[4]), fmax4(rv[5])),
                                   fmaxf(fmax4(rv[6]), fmax4(rv[7]))));
            if (tid < 512) {
                float e0 = __nv_expf(__fsub_rn(sm.logits[2*tid],     m_r));
                float e1 = __nv_expf(__fsub_rn(sm.logits[2*tid + 1], m_r));
                float v = __fadd_rn(e0, e1);
                v = __fadd_rn(v, __shfl_down_sync(FULLM, v, 16));
                v = __fadd_rn(v, __shfl_down_sync(FULLM, v, 8));
                v = __fadd_rn(v, __shfl_down_sync(FULLM, v, 4));
                v = __fadd_rn(v, __shfl_down_sync(FULLM, v, 2));
                v = __fadd_rn(v, __shfl_down_sync(FULLM, v, 1));
                if (lane == 0) sm.redv2[warp] = v;
            }
        }
        __syncthreads();

        // ---- P9 (duplicated): L (FROZEN tree), lp, per-warp argmax ----
        float L_r;
        {
            float4 a0 = *(float4*)&sm.redv2[0];
            float4 a1 = *(float4*)&sm.redv2[4];
            float4 a2 = *(float4*)&sm.redv2[8];
            float4 a3 = *(float4*)&sm.redv2[12];
            a0.x = __fadd_rn(a0.x, a2.x); a0.y = __fadd_rn(a0.y, a2.y);
            a0.z = __fadd_rn(a0.z, a2.z); a0.w = __fadd_rn(a0.w, a2.w);
            a1.x = __fadd_rn(a1.x, a3.x); a1.y = __fadd_rn(a1.y, a3.y);
            a1.z = __fadd_rn(a1.z, a3.z); a1.w = __fadd_rn(a1.w, a3.w);
            a0.x = __fadd_rn(a0.x, a1.x); a0.y = __fadd_rn(a0.y, a1.y);
            a0.z = __fadd_rn(a0.z, a1.z); a0.w = __fadd_rn(a0.w, a1.w);
            a0.x = __fadd_rn(a0.x, a0.z); a0.y = __fadd_rn(a0.y, a0.w);
            L_r = __nv_logf(__fadd_rn(a0.x, a0.y));

            float lp = __fsub_rn(__fsub_rn(sm.logits[tid], m_r), L_r);
            float v = lp;
            int idx = tid;
#pragma unroll
            for (int off = 16; off; off >>= 1) {
                float ov = __shfl_xor_sync(FULLM, v, off);
                int   oi = __shfl_xor_sync(FULLM, idx, off);
                if (ov > v || (ov == v && oi < idx)) { v = ov; idx = oi; }
            }
            if (lane == 0) { sm.redv3[warp] = v; sm.redi[warp] = idx; }
        }
        __syncthreads();

        // ---- P10 (duplicated): city lexmax (order-free); state; next q ----
        {
            float bv = sm.redv3[0]; int bi = sm.redi[0];
#pragma unroll
            for (int w2 = 1; w2 < 32; w2++) {
                float ov = sm.redv3[w2]; int oi = sm.redi[w2];
                if (ov > bv || (ov == bv && oi < bi)) { bv = ov; bi = oi; }
            }
            int city = bi;
            if (t == 0) {
                first_r = city;
                if (tid < 128) pf_r = projb[(size_t)first_r * PC + 384 + tid];
            }
            if (warp < 16 && (city >> 5) == lw) wm |= 1u << (city & 31);
            if (tid == 0 && rank == 0) {
                logp_sum += (double)__fsub_rn(__fsub_rn(sm.logits[city], m_r), L_r);
                out[BB + b * SS + t] = (float)city;
            }
            if (tid < 128) {
                float pl = projb[(size_t)city * PC + 512 + tid];
                sm.q[tid] = sm.hhat[tid] + (pf_r + pl);
            }
        }
        __syncthreads();
    }

    if (tid == 0 && rank == 0) out[b] = (float)logp_sum;
}

// ============================================================================
extern "C" void kernel_launch(void* const* d_in, const int* in_sizes, int n_in,
                              void* d_out, int out_size) {
    const float* enc    = (const float*)d_in[0];
    const float* W_ctx  = (const float*)d_in[1];
    const float* W_upd  = (const float*)d_in[2];
    const float* W_node = (const float*)d_in[3];
    const float* W_out  = (const float*)d_in[4];
    const float* W_ph   = (const float*)d_in[5];
    float* out = (float*)d_out;

    static const int GEMM_SMEM = (128 * 65 + 128 * 128) * sizeof(float);
    static const int DEC_SMEM  = (int)sizeof(DS);
    cudaFuncSetAttribute(gemm_kernel,   cudaFuncAttributeMaxDynamicSharedMemorySize, GEMM_SMEM);
    cudaFuncSetAttribute(decode_kernel, cudaFuncAttributeMaxDynamicSharedMemorySize, DEC_SMEM);

    prep_kernel<<<16, 1024>>>(W_node, W_upd);
    gemm_kernel<<<dim3((BB * SS) / 64, PC / 128), 256, GEMM_SMEM>>>(enc);
    decode_kernel<<<BB * 2, 1024, DEC_SMEM>>>(enc, W_ctx, W_upd, W_out, W_ph, out);
}

// round 14
// speedup vs baseline: 1.7731x; 1.7731x over previous
#include <cuda_runtime.h>
#include <math.h>
#include <stdint.h>

#define BB 64
#define SS 1024
#define EE 128
#define PC 640              // gK(128) gV(128) logitK(128) P1(128) P2(128)
#define INV_SQRT_E  0.08838834764831845f
#define FULLM 0xffffffffu

extern "C" __device__ float __nv_expf(float);
extern "C" __device__ float __nv_logf(float);

// XLA f32 tanh (frozen numerics — do not touch)
__device__ __forceinline__ float xla_tanh(float x) {
    float xc = fminf(fmaxf(x, -7.99881172180175781f), 7.99881172180175781f);
    float x2 = __fmul_rn(xc, xc);
    float p = __fadd_rn(__fmul_rn(x2, -2.76076847742355e-16f), 2.00018790482477e-13f);
    p = __fadd_rn(__fmul_rn(x2, p), -8.60467152213735e-11f);
    p = __fadd_rn(__fmul_rn(x2, p), 5.12229709037114e-08f);
    p = __fadd_rn(__fmul_rn(x2, p), 1.48572235717979e-05f);
    p = __fadd_rn(__fmul_rn(x2, p), 6.37261928875436e-04f);
    p = __fadd_rn(__fmul_rn(x2, p), 4.89352455891786e-03f);
    p = __fmul_rn(xc, p);
    float q = __fadd_rn(__fmul_rn(x2, 1.19825839466702e-06f), 1.18534705686654e-04f);
    q = __fadd_rn(__fmul_rn(x2, q), 2.26843463243900e-03f);
    q = __fadd_rn(__fmul_rn(x2, q), 4.89352518554385e-03f);
    float r = __fdiv_rn(p, q);
    return (fabsf(x) < 0.0004f) ? x : r;
}

__device__ __forceinline__ float fmax4(float4 v) {
    return fmaxf(fmaxf(v.x, v.y), fmaxf(v.z, v.w));
}

__device__ float g_Wall[128 * PC];
__device__ float g_proj[(size_t)BB * SS * PC];   // 168 MB

// ============================================================================
__global__ void prep_kernel(const float* __restrict__ W_node,
                            const float* __restrict__ W_upd) {
    int tid = blockIdx.x * blockDim.x + threadIdx.x;
    int stride = blockDim.x * gridDim.x;
    for (int idx = tid; idx < 128 * 384; idx += stride) {
        int k = idx / 384, c = idx % 384;
        g_Wall[k * PC + c] = W_node[k * 384 + c];
    }
    for (int idx = tid; idx < 256 * 128; idx += stride) {
        int k2 = idx >> 7, j = idx & 127;
        float v = W_upd[idx];
        if (k2 < 128) g_Wall[k2 * PC + 384 + j] = v;
        else          g_Wall[(k2 - 128) * PC + 512 + j] = v;
    }
}

// ============================================================================
__global__ __launch_bounds__(256) void gemm_kernel(const float* __restrict__ A) {
    extern __shared__ float sh[];
    float* As = sh;              // [128][65]
    float* Bs = sh + 128 * 65;   // [128][128]
    int row0 = blockIdx.x * 64, col0 = blockIdx.y * 128, tid = threadIdx.x;

    for (int idx = tid; idx < 64 * 128; idx += 256) {
        int r = idx >> 7, k = idx & 127;
        As[k * 65 + r] = A[(size_t)(row0 + r) * 128 + k];
    }
    for (int idx = tid; idx < 128 * 128; idx += 256) {
        int k = idx >> 7, c = idx & 127;
        Bs[k * 128 + c] = g_Wall[k * PC + col0 + c];
    }
    __syncthreads();

    int tx = tid & 15, ty = tid >> 4;
    int r0 = ty * 4, c0 = tx * 8;
    float acc[4][8];
#pragma unroll
    for (int i = 0; i < 4; i++)
#pragma unroll
        for (int j = 0; j < 8; j++) acc[i][j] = 0.f;
#pragma unroll 8
    for (int k = 0; k < 128; k++) {
        float a0 = As[k*65+r0], a1 = As[k*65+r0+1], a2 = As[k*65+r0+2], a3 = As[k*65+r0+3];
        float4 b0 = *(float4*)&Bs[k*128+c0];
        float4 b1 = *(float4*)&Bs[k*128+c0+4];
        float bb[8] = {b0.x,b0.y,b0.z,b0.w,b1.x,b1.y,b1.z,b1.w};
#pragma unroll
        for (int j = 0; j < 8; j++) {
            acc[0][j] += a0*bb[j]; acc[1][j] += a1*bb[j];
            acc[2][j] += a2*bb[j]; acc[3][j] += a3*bb[j];
        }
    }
#pragma unroll
    for (int i = 0; i < 4; i++) {
        size_t o = (size_t)(row0+r0+i)*PC + col0 + c0;
        *(float4*)&g_proj[o]   = make_float4(acc[i][0],acc[i][1],acc[i][2],acc[i][3]);
        *(float4*)&g_proj[o+4] = make_float4(acc[i][4],acc[i][5],acc[i][6],acc[i][7]);
    }
}

// ============================================================================
// Decode: single CTA per batch (cluster reverted). Ordered active-list
// compaction in the three streaming phases; compat poisoned once per masked
// city; evbuf separates exp values. All frozen chains bit-identical to R12.
// ============================================================================
struct DS {
    float wout[128 * 128];    // 64 KB
    float compat[8 * 1032];   // cv; masked slots hold -inf persistently
    float evbuf[8 * 1032];    // exp values (P3 out, P4 in)
    float part[32 * 128];
    float logits[1024];
    float q[128], hhat[128], phq[128], heads[128], glim[128];
    float redv8[8 * 32];      // [head][warp]
    float redv[32];
    float redv2[32];
    float redv3[32];
    int   redi[32];
    unsigned char alist[32 * 32];  // per-warp ascending active city list
};

__global__ __launch_bounds__(1024, 1) void decode_kernel(
    const float* __restrict__ enc,
    const float* __restrict__ W_ctx,
    const float* __restrict__ W_upd,
    const float* __restrict__ W_out,
    const float* __restrict__ W_ph,
    float* __restrict__ out)
{
    extern __shared__ char smem_raw[];
    DS& sm = *reinterpret_cast<DS*>(smem_raw);

    const int b = blockIdx.x, tid = threadIdx.x;
    const int lane = tid & 31, warp = tid >> 5;
    const float NEGINF = -INFINITY;

    const float* __restrict__ projb = g_proj + (size_t)b * SS * PC;
    const float* __restrict__ encb  = enc + (size_t)b * SS * EE;

    // ---- init (numerics identical to R12) ----
    for (int idx = tid; idx < 128 * 128; idx += 1024)
        sm.wout[idx] = W_out[idx];
    sm.alist[warp * 32 + lane] = (unsigned char)lane;   // all active
    {
        int e = tid & 127, g = tid >> 7;
        float acc = 0.f;
        for (int i = 0; i < 128; i++)
            acc += encb[(size_t)(g * 128 + i) * EE + e];
        sm.part[g * 128 + e] = acc;
    }
    __syncthreads();
    if (tid < 128) {
        float m = 0.f;
#pragma unroll
        for (int g = 0; g < 8; g++) m += sm.part[g * 128 + tid];
        sm.q[tid] = m * (1.0f / 1024.0f);
    }
    __syncthreads();
    if (tid < 128) {
        float h = 0.f;
#pragma unroll 8
        for (int k = 0; k < 128; k++) h += sm.q[k] * W_ctx[k * 128 + tid];
        sm.hhat[tid] = h;
    } else if (tid < 256) {
        int e = tid - 128;
        float p = 0.f;
#pragma unroll 8
        for (int k = 0; k < 256; k++) p += W_ph[k] * W_upd[k * 128 + e];
        sm.phq[e] = p;
    }
    __syncthreads();
    if (tid < 128) sm.q[tid] = sm.hhat[tid] + sm.phq[tid];
    __syncthreads();

    unsigned wm = 0u;        // per-warp mask bits
    int first_r = 0;
    float pf_r = 0.f;
    double logp_sum = 0.0;

    for (int t = 0; t < SS; t++) {
        const unsigned char* lst = &sm.alist[warp * 32];
        int cnt = 32 - __popc(wm);

        // ---- P1: compat over active list (chunks of 8) + per-head max ----
        {
            float4 qv = *(float4*)&sm.q[lane * 4];
            int h = lane >> 2;
            float mx = NEGINF;
            for (int j0 = 0; j0 < cnt; j0 += 8) {
                float4 g_[8];
#pragma unroll
                for (int k = 0; k < 8; k++) {
                    int jj = j0 + k;
                    int jc = jj < cnt ? jj : cnt - 1;
                    int ii = lst[jc];
                    g_[k] = *(const float4*)(projb + (size_t)(warp * 32 + ii) * PC + lane * 4);
                }
#pragma unroll
                for (int k = 0; k < 8; k++) {
                    int jj = j0 + k;
                    if (jj < cnt) {
                        int ii = lst[jj];
                        float4 g = g_[k];
                        float v = g.x*qv.x + g.y*qv.y + g.z*qv.z + g.w*qv.w;
                        v += __shfl_xor_sync(FULLM, v, 1);
                        v += __shfl_xor_sync(FULLM, v, 2);
                        float cv = v * 0.25f;
                        mx = fmaxf(mx, cv);
                        if ((lane & 3) == 0) sm.compat[h * 1032 + warp * 32 + ii] = cv;
                    }
                }
            }
            if ((lane & 3) == 0) sm.redv8[h * 32 + warp] = mx;
        }
        __syncthreads();

        // ---- P3: hm (order-free fmax) + frozen exp chain -> evbuf + warp sum ----
        {
            int gh = tid >> 7, j = tid & 127;
            const float4* r8 = (const float4*)&sm.redv8[gh * 32];
            float hm = fmaxf(fmaxf(fmax4(r8[0]), fmax4(r8[1])),
                             fmaxf(fmax4(r8[2]), fmax4(r8[3])));
            hm = fmaxf(hm, fmaxf(fmaxf(fmax4(r8[4]), fmax4(r8[5])),
                                 fmaxf(fmax4(r8[6]), fmax4(r8[7]))));
            float se = 0.f;
#pragma unroll
            for (int ii = 0; ii < 8; ii++) {
                int idx = gh * 1032 + j + ii * 128;
                float ev = __nv_expf(sm.compat[idx] - hm);   // masked: exp(-inf)=+0
                sm.evbuf[idx] = ev;
                se += ev;                                     // frozen serial chain
            }
#pragma unroll
            for (int off = 16; off; off >>= 1)
                se += __shfl_xor_sync(FULLM, se, off);
            if (lane == 0) sm.redv2[warp] = se;
        }
        __syncthreads();

        // ---- P4: invs replay + heads partials over active list (chunks of 8) ----
        {
            int h = lane >> 2;
            float s4 = sm.redv2[h*4] + sm.redv2[h*4+1] + sm.redv2[h*4+2] + sm.redv2[h*4+3];
            float invs = 1.0f / s4;
            float4 acc = make_float4(0.f, 0.f, 0.f, 0.f);
            for (int j0 = 0; j0 < cnt; j0 += 8) {
                float4 g_[8];
#pragma unroll
                for (int k = 0; k < 8; k++) {
                    int jj = j0 + k;
                    int jc = jj < cnt ? jj : cnt - 1;
                    int ii = lst[jc];
                    g_[k] = *(const float4*)(projb + (size_t)(warp * 32 + ii) * PC + 128 + lane * 4);
                }
#pragma unroll
                for (int k = 0; k < 8; k++) {
                    int jj = j0 + k;
                    if (jj < cnt) {
                        int ii = lst[jj];
                        float a = sm.evbuf[h * 1032 + warp * 32 + ii] * invs;
                        float4 g = g_[k];
                        acc.x += a*g.x; acc.y += a*g.y; acc.z += a*g.z; acc.w += a*g.w;
                    }
                }
            }
            ((float4*)&sm.part[warp * 128])[lane] = acc;
        }
        __syncthreads();

        // ---- P5: heads reduce (frozen 2-stage order) ----
        if (tid < 128) {
            float hsum = 0.f;
#pragma unroll
            for (int g = 0; g < 8; g++) {
                float pg = sm.part[(g*4+0)*128+tid] + sm.part[(g*4+1)*128+tid]
                         + sm.part[(g*4+2)*128+tid] + sm.part[(g*4+3)*128+tid];
                hsum += pg;
            }
            sm.heads[tid] = hsum;
        }
        __syncthreads();

        // ---- P6: glimpse (frozen chain) ----
        if (tid < 128) {
            float gl = 0.f;
#pragma unroll 8
            for (int f = 0; f < 128; f++) gl += sm.heads[f] * sm.wout[f*128+tid];
            sm.glim[tid] = gl;
        }
        __syncthreads();

        // ---- P7: logit dots over active list (3-shfl butterfly) + tanh ----
        {
            int g = lane >> 3, j = lane & 7;
            float4 h0 = *(float4*)&sm.glim[(j     ) * 4];
            float4 h1 = *(float4*)&sm.glim[(j +  8) * 4];
            float4 h2 = *(float4*)&sm.glim[(j + 16) * 4];
            float4 h3 = *(float4*)&sm.glim[(j + 24) * 4];
            int nch = (cnt + 3) >> 2;
            for (int m = 0; m < nch; m++) {
                int jj = m * 4 + g;
                bool val = jj < cnt;
                int ii = lst[val ? jj : 0];
                int s = warp * 32 + ii;
                const float* row = projb + (size_t)s * PC + 256;
                float4 gA = *(const float4*)(row + (j     ) * 4);
                float4 gB = *(const float4*)(row + (j +  8) * 4);
                float4 gC = *(const float4*)(row + (j + 16) * 4);
                float4 gD = *(const float4*)(row + (j + 24) * 4);
                float dA = gA.x*h0.x + gA.y*h0.y + gA.z*h0.z + gA.w*h0.w;
                float dB = gB.x*h1.x + gB.y*h1.y + gB.z*h1.z + gB.w*h1.w;
                float dC = gC.x*h2.x + gC.y*h2.y + gC.z*h2.z + gC.w*h2.w;
                float dD = gD.x*h3.x + gD.y*h3.y + gD.z*h3.z + gD.w*h3.w;
                float t16a = dA + dC;
                float t16b = dB + dD;
                float v = t16a + t16b;
                v += __shfl_xor_sync(FULLM, v, 4);
                v += __shfl_xor_sync(FULLM, v, 2);
                v += __shfl_xor_sync(FULLM, v, 1);
                if (val && j == 0) sm.logits[s] = v;   // raw dot staged
            }
            __syncwarp();
            {
                int s = warp * 32 + lane;
                bool active = !((wm >> lane) & 1u);
                float v = NEGINF;
                if (active) {
                    float raw = sm.logits[s];
                    float lv = __fmul_rn(10.0f, xla_tanh(__fmul_rn(raw, INV_SQRT_E)));
                    sm.logits[s] = lv;
                    v = lv;
                }
                // masked slots: logits[s] already -inf (poisoned in P10)
#pragma unroll
                for (int off = 16; off; off >>= 1)
                    v = fmaxf(v, __shfl_xor_sync(FULLM, v, off));
                if (lane == 0) sm.redv[warp] = v;
            }
        }
        __syncthreads();

        // ---- P8: m (order-free fmax); frozen pair-exp tree ----
        float m_r;
        {
            const float4* rv = (const float4*)&sm.redv[0];
            m_r = fmaxf(fmaxf(fmax4(rv[0]), fmax4(rv[1])),
                        fmaxf(fmax4(rv[2]), fmax4(rv[3])));
            m_r = fmaxf(m_r, fmaxf(fmaxf(fmax4(rv[4]), fmax4(rv[5])),
                                   fmaxf(fmax4(rv[6]), fmax4(rv[7]))));
            if (tid < 512) {
                float e0 = __nv_expf(__fsub_rn(sm.logits[2*tid],     m_r));
                float e1 = __nv_expf(__fsub_rn(sm.logits[2*tid + 1], m_r));
                float v = __fadd_rn(e0, e1);
                v = __fadd_rn(v, __shfl_down_sync(FULLM, v, 16));
                v = __fadd_rn(v, __shfl_down_sync(FULLM, v, 8));
                v = __fadd_rn(v, __shfl_down_sync(FULLM, v, 4));
                v = __fadd_rn(v, __shfl_down_sync(FULLM, v, 2));
                v = __fadd_rn(v, __shfl_down_sync(FULLM, v, 1));
                if (lane == 0) sm.redv2[warp] = v;
            }
        }
        __syncthreads();

        // ---- P9: L (FROZEN tree), lp, per-warp argmax ----
        float L_r;
        {
            float4 a0 = *(float4*)&sm.redv2[0];
            float4 a1 = *(float4*)&sm.redv2[4];
            float4 a2 = *(float4*)&sm.redv2[8];
            float4 a3 = *(float4*)&sm.redv2[12];
            a0.x = __fadd_rn(a0.x, a2.x); a0.y = __fadd_rn(a0.y, a2.y);
            a0.z = __fadd_rn(a0.z, a2.z); a0.w = __fadd_rn(a0.w, a2.w);
            a1.x = __fadd_rn(a1.x, a3.x); a1.y = __fadd_rn(a1.y, a3.y);
            a1.z = __fadd_rn(a1.z, a3.z); a1.w = __fadd_rn(a1.w, a3.w);
            a0.x = __fadd_rn(a0.x, a1.x); a0.y = __fadd_rn(a0.y, a1.y);
            a0.z = __fadd_rn(a0.z, a1.z); a0.w = __fadd_rn(a0.w, a1.w);
            a0.x = __fadd_rn(a0.x, a0.z); a0.y = __fadd_rn(a0.y, a0.w);
            L_r = __nv_logf(__fadd_rn(a0.x, a0.y));

            float lp = __fsub_rn(__fsub_rn(sm.logits[tid], m_r), L_r);
            float v = lp;
            int idx = tid;
#pragma unroll
            for (int off = 16; off; off >>= 1) {
                float ov = __shfl_xor_sync(FULLM, v, off);
                int   oi = __shfl_xor_sync(FULLM, idx, off);
                if (ov > v || (ov == v && oi < idx)) { v = ov; idx = oi; }
            }
            if (lane == 0) { sm.redv3[warp] = v; sm.redi[warp] = idx; }
        }
        __syncthreads();

        // ---- P10: city (serial lexmax, order-free); poison; rebuild; next q ----
        {
            float bv = sm.redv3[0]; int bi = sm.redi[0];
#pragma unroll
            for (int w2 = 1; w2 < 32; w2++) {
                float ov = sm.redv3[w2]; int oi = sm.redi[w2];
                if (ov > bv || (ov == bv && oi < bi)) { bv = ov; bi = oi; }
            }
            int city = bi;
            if (t == 0) {
                first_r = city;
                if (tid < 128) pf_r = projb[(size_t)first_r * PC + 384 + tid];
            }
            if ((city >> 5) == warp) wm |= 1u << (city & 31);
            if (tid == 0) {
                logp_sum += (double)__fsub_rn(__fsub_rn(sm.logits[city], m_r), L_r);
                out[BB + b * SS + t] = (float)city;
                sm.logits[city] = NEGINF;              // poison once
            }
            if (tid < 8) sm.compat[tid * 1032 + city] = NEGINF;  // poison once
            // rebuild this warp's ascending active list from updated wm
            {
                unsigned act = ~wm;
                if ((act >> lane) & 1u) {
                    int pos = __popc(act & ((1u << lane) - 1u));
                    sm.alist[warp * 32 + pos] = (unsigned char)lane;
                }
            }
            if (tid < 128) {
                float pl = projb[(size_t)city * PC + 512 + tid];
                sm.q[tid] = sm.hhat[tid] + (pf_r + pl);
            }
        }
        __syncthreads();
    }

    if (tid == 0) out[b] = (float)logp_sum;
}

// ============================================================================
extern "C" void kernel_launch(void* const* d_in, const int* in_sizes, int n_in,
                              void* d_out, int out_size) {
    const float* enc    = (const float*)d_in[0];
    const float* W_ctx  = (const float*)d_in[1];
    const float* W_upd  = (const float*)d_in[2];
    const float* W_node = (const float*)d_in[3];
    const float* W_out  = (const float*)d_in[4];
    const float* W_ph   = (const float*)d_in[5];
    float* out = (float*)d_out;

    static const int GEMM_SMEM = (128 * 65 + 128 * 128) * sizeof(float);
    static const int DEC_SMEM  = (int)sizeof(DS);
    cudaFuncSetAttribute(gemm_kernel,   cudaFuncAttributeMaxDynamicSharedMemorySize, GEMM_SMEM);
    cudaFuncSetAttribute(decode_kernel, cudaFuncAttributeMaxDynamicSharedMemorySize, DEC_SMEM);

    prep_kernel<<<16, 1024>>>(W_node, W_upd);
    gemm_kernel<<<dim3((BB * SS) / 64, PC / 128), 256, GEMM_SMEM>>>(enc);
    decode_kernel<<<BB, 1024, DEC_SMEM>>>(enc, W_ctx, W_upd, W_out, W_ph, out);
}